// round 4
// baseline (speedup 1.0000x reference)
#include <cuda_runtime.h>

// Shapes (fixed by the problem)
static constexpr int Bc  = 2;
static constexpr int Sc  = 2048;
static constexpr int DMc = 512;
static constexpr int Hc  = 8;
static constexpr int DHc = 64;
static constexpr int BHc = Bc * Hc;          // 16
static constexpr int Mrows = Bc * Sc;        // 4096

// -------- device scratch (no allocations allowed) --------
__device__ float g_qp[Mrows * DMc];          // 8 MB
__device__ float g_kp[Mrows * DMc];          // 8 MB
__device__ float g_vp[Mrows * DMc];          // 8 MB
__device__ float g_outpre[Mrows * DMc];      // 8 MB  (attn @ V, in (b,s,dm) layout)
__device__ float g_a[BHc * Sc];
__device__ float g_b[BHc * Sc];
__device__ float g_rmax[BHc * Sc];
__device__ float g_rinv[BHc * Sc];

// ============================================================
// Generic 128x128 tiled SGEMM body: C = A(MxK) @ W(KxN) + bias
// blockDim = (16,16); grid = (N/128, M/128). All dims % 128 == 0, K % 8 == 0.
// ============================================================
__device__ __forceinline__ void sgemm128(const float* __restrict__ A,
                                         const float* __restrict__ W,
                                         const float* __restrict__ bias,
                                         float* __restrict__ C,
                                         int N, int K)
{
    __shared__ __align__(16) float As[8][128];
    __shared__ __align__(16) float Ws[8][132];

    const int tid  = threadIdx.y * 16 + threadIdx.x;
    const int mb   = blockIdx.y * 128;
    const int nb   = blockIdx.x * 128;
    const int arow = tid >> 1;
    const int ak4  = (tid & 1) << 2;
    const int wrow = tid >> 5;
    const int wn4  = (tid & 31) << 2;
    const int m0   = threadIdx.y << 3;
    const int n0   = threadIdx.x << 3;

    float acc[8][8];
#pragma unroll
    for (int i = 0; i < 8; i++)
#pragma unroll
        for (int j = 0; j < 8; j++) acc[i][j] = 0.f;

    for (int k0 = 0; k0 < K; k0 += 8) {
        float4 av = *(const float4*)(A + (size_t)(mb + arow) * K + k0 + ak4);
        As[ak4 + 0][arow] = av.x;
        As[ak4 + 1][arow] = av.y;
        As[ak4 + 2][arow] = av.z;
        As[ak4 + 3][arow] = av.w;
        *(float4*)(&Ws[wrow][wn4]) =
            *(const float4*)(W + (size_t)(k0 + wrow) * N + nb + wn4);
        __syncthreads();

#pragma unroll
        for (int kk = 0; kk < 8; kk++) {
            float af[8], wf[8];
            *(float4*)(af)     = *(const float4*)(&As[kk][m0]);
            *(float4*)(af + 4) = *(const float4*)(&As[kk][m0 + 4]);
            *(float4*)(wf)     = *(const float4*)(&Ws[kk][n0]);
            *(float4*)(wf + 4) = *(const float4*)(&Ws[kk][n0 + 4]);
#pragma unroll
            for (int i = 0; i < 8; i++)
#pragma unroll
                for (int j = 0; j < 8; j++)
                    acc[i][j] = fmaf(af[i], wf[j], acc[i][j]);
        }
        __syncthreads();
    }

#pragma unroll
    for (int i = 0; i < 8; i++) {
        float* crow = C + (size_t)(mb + m0 + i) * N + nb + n0;
#pragma unroll
        for (int j = 0; j < 8; j += 4) {
            float4 o;
            o.x = acc[i][j + 0] + bias[nb + n0 + j + 0];
            o.y = acc[i][j + 1] + bias[nb + n0 + j + 1];
            o.z = acc[i][j + 2] + bias[nb + n0 + j + 2];
            o.w = acc[i][j + 3] + bias[nb + n0 + j + 3];
            *(float4*)(crow + j) = o;
        }
    }
}

// K1: fused Q/K/V projections. grid = (4, 32, 3)
__global__ __launch_bounds__(256)
void proj_kernel(const float* __restrict__ q, const float* __restrict__ k,
                 const float* __restrict__ v,
                 const float* __restrict__ Wq, const float* __restrict__ Wk,
                 const float* __restrict__ Wv,
                 const float* __restrict__ bq, const float* __restrict__ bk,
                 const float* __restrict__ bv)
{
    const float* A; const float* W; const float* bias; float* C;
    if (blockIdx.z == 0)      { A = q; W = Wq; bias = bq; C = g_qp; }
    else if (blockIdx.z == 1) { A = k; W = Wk; bias = bk; C = g_kp; }
    else                      { A = v; W = Wv; bias = bv; C = g_vp; }
    sgemm128(A, W, bias, C, DMc, DMc);
}

// K2: a = qp@Wa + ba, b = qp@Wb + bb, stored as (B,H,S). grid = 512, block = 256.
__global__ __launch_bounds__(256)
void ab_kernel(const float* __restrict__ Wa, const float* __restrict__ ba,
               const float* __restrict__ Wb, const float* __restrict__ bb)
{
    const int warp = threadIdx.x >> 5;
    const int lane = threadIdx.x & 31;
    const int row  = blockIdx.x * 8 + warp;     // 0..4095
    const int b    = row / Sc;
    const int s    = row - b * Sc;

    float acca[8], accb[8];
#pragma unroll
    for (int h = 0; h < 8; h++) { acca[h] = 0.f; accb[h] = 0.f; }

    for (int t = 0; t < DMc / 32; t++) {
        int d = lane + t * 32;
        float x = g_qp[(size_t)row * DMc + d];
#pragma unroll
        for (int h = 0; h < 8; h++) {
            acca[h] = fmaf(x, Wa[d * Hc + h], acca[h]);
            accb[h] = fmaf(x, Wb[d * Hc + h], accb[h]);
        }
    }
#pragma unroll
    for (int h = 0; h < 8; h++) {
#pragma unroll
        for (int o = 16; o > 0; o >>= 1) {
            acca[h] += __shfl_down_sync(0xffffffff, acca[h], o);
            accb[h] += __shfl_down_sync(0xffffffff, accb[h], o);
        }
    }
    if (lane == 0) {
#pragma unroll
        for (int h = 0; h < 8; h++) {
            g_a[(b * Hc + h) * Sc + s] = acca[h] + ba[h];
            g_b[(b * Hc + h) * Sc + s] = accb[h] + bb[h];
        }
    }
}

// K3: raw logits -> attn region. grid = (16 ktile, 16 qtile, 16 bh), block (16,16).
__global__ __launch_bounds__(256)
void logits_kernel(const float* __restrict__ xdiff, const int* __restrict__ mask,
                   float* __restrict__ attn)
{
    __shared__ __align__(16) float Qs[32][132];
    __shared__ __align__(16) float Ks[32][132];

    const int bh = blockIdx.z;
    const int b  = bh >> 3;
    const int h  = bh & 7;
    const int qb = blockIdx.y * 128;
    const int kb = blockIdx.x * 128;
    const int tid = threadIdx.y * 16 + threadIdx.x;
    const int q0  = threadIdx.y << 3;
    const int k0  = threadIdx.x << 3;

    float acc[8][8];
#pragma unroll
    for (int i = 0; i < 8; i++)
#pragma unroll
        for (int j = 0; j < 8; j++) acc[i][j] = 0.f;

    for (int dc = 0; dc < DHc; dc += 32) {
#pragma unroll
        for (int i = 0; i < 4; i++) {
            int f  = i * 256 + tid;        // 0..1023
            int r  = f >> 3;               // 0..127 (tile row)
            int d4 = (f & 7) << 2;         // 0..28
            float4 qv = *(const float4*)(g_qp + (size_t)(b * Sc + qb + r) * DMc + h * DHc + dc + d4);
            Qs[d4 + 0][r] = qv.x; Qs[d4 + 1][r] = qv.y;
            Qs[d4 + 2][r] = qv.z; Qs[d4 + 3][r] = qv.w;
            float4 kv = *(const float4*)(g_kp + (size_t)(b * Sc + kb + r) * DMc + h * DHc + dc + d4);
            Ks[d4 + 0][r] = kv.x; Ks[d4 + 1][r] = kv.y;
            Ks[d4 + 2][r] = kv.z; Ks[d4 + 3][r] = kv.w;
        }
        __syncthreads();

#pragma unroll
        for (int d = 0; d < 32; d++) {
            float qf[8], kf[8];
            *(float4*)(qf)     = *(const float4*)(&Qs[d][q0]);
            *(float4*)(qf + 4) = *(const float4*)(&Qs[d][q0 + 4]);
            *(float4*)(kf)     = *(const float4*)(&Ks[d][k0]);
            *(float4*)(kf + 4) = *(const float4*)(&Ks[d][k0 + 4]);
#pragma unroll
            for (int i = 0; i < 8; i++)
#pragma unroll
                for (int j = 0; j < 8; j++)
                    acc[i][j] = fmaf(qf[i], kf[j], acc[i][j]);
        }
        __syncthreads();
    }

    // epilogue: scale + mask + a*xd + b*xd^2, write raw logits
    const int kq = kb + k0;
#pragma unroll
    for (int i = 0; i < 8; i++) {
        const int q  = qb + q0 + i;
        const float aq = g_a[bh * Sc + q];
        const float bq = g_b[bh * Sc + q];
        const float* xrow = xdiff + ((size_t)b * Sc + q) * Sc + kq;
        const int*   mrow = mask + b * Sc + kq;
        float* orow = attn + ((size_t)bh * Sc + q) * Sc + kq;
#pragma unroll
        for (int j = 0; j < 8; j += 4) {
            float4 xd = *(const float4*)(xrow + j);
            int4   mv = *(const int4*)(mrow + j);
            float4 o;
            o.x = acc[i][j + 0] * 0.125f + (float)mv.x * -1e9f + aq * xd.x + bq * xd.x * xd.x;
            o.y = acc[i][j + 1] * 0.125f + (float)mv.y * -1e9f + aq * xd.y + bq * xd.y * xd.y;
            o.z = acc[i][j + 2] * 0.125f + (float)mv.z * -1e9f + aq * xd.z + bq * xd.z * xd.z;
            o.w = acc[i][j + 3] * 0.125f + (float)mv.w * -1e9f + aq * xd.w + bq * xd.w * xd.w;
            *(float4*)(orow + j) = o;
        }
    }
}

// K4: per-row max + 1/sum(exp). grid = BH*S, block = 256.
__global__ __launch_bounds__(256)
void stats_kernel(const float* __restrict__ attn)
{
    __shared__ float red[256];
    const int r = blockIdx.x;
    const float* row = attn + (size_t)r * Sc;
    const int tid = threadIdx.x;

    float vals[8];
    float m = -1e30f;
#pragma unroll
    for (int i = 0; i < 8; i++) {
        vals[i] = row[tid + i * 256];
        m = fmaxf(m, vals[i]);
    }
    red[tid] = m;
    __syncthreads();
    for (int s2 = 128; s2 > 0; s2 >>= 1) {
        if (tid < s2) red[tid] = fmaxf(red[tid], red[tid + s2]);
        __syncthreads();
    }
    m = red[0];
    __syncthreads();

    float s = 0.f;
#pragma unroll
    for (int i = 0; i < 8; i++) s += __expf(vals[i] - m);
    red[tid] = s;
    __syncthreads();
    for (int s2 = 128; s2 > 0; s2 >>= 1) {
        if (tid < s2) red[tid] += red[tid + s2];
        __syncthreads();
    }
    if (tid == 0) {
        g_rmax[r] = m;
        g_rinv[r] = 1.0f / red[0];
    }
}

// K5: normalize attn in-place + out = attn @ Vh -> g_outpre (b,s,dm layout).
// grid = (16 qtile, 16 bh), block (16,16).
__global__ __launch_bounds__(256)
void attnv_kernel(float* __restrict__ attn)
{
    __shared__ __align__(16) float Ps[32][132];
    __shared__ __align__(16) float Vs[32][68];

    const int bh = blockIdx.y;
    const int b  = bh >> 3;
    const int h  = bh & 7;
    const int qb = blockIdx.x * 128;
    const int tid = threadIdx.y * 16 + threadIdx.x;
    const int q0  = threadIdx.y << 3;   // 0..120
    const int d0  = threadIdx.x << 2;   // 0..60

    float acc[8][4];
#pragma unroll
    for (int i = 0; i < 8; i++)
#pragma unroll
        for (int j = 0; j < 4; j++) acc[i][j] = 0.f;

    for (int kt = 0; kt < Sc; kt += 32) {
        // load raw logits tile 128x32, normalize, write back, stage transposed
#pragma unroll
        for (int i = 0; i < 4; i++) {
            int f  = i * 256 + tid;
            int qq = f >> 3;
            int k4 = (f & 7) << 2;
            int q  = qb + qq;
            size_t off = ((size_t)bh * Sc + q) * Sc + kt + k4;
            float4 L = *(const float4*)(attn + off);
            float m   = g_rmax[bh * Sc + q];
            float inv = g_rinv[bh * Sc + q];
            float4 p;
            p.x = __expf(L.x - m) * inv;
            p.y = __expf(L.y - m) * inv;
            p.z = __expf(L.z - m) * inv;
            p.w = __expf(L.w - m) * inv;
            *(float4*)(attn + off) = p;
            Ps[k4 + 0][qq] = p.x; Ps[k4 + 1][qq] = p.y;
            Ps[k4 + 2][qq] = p.z; Ps[k4 + 3][qq] = p.w;
        }
        // load V tile 32x64 (vh[b,h,k,d] = vp[b,k,h*64+d])
#pragma unroll
        for (int i = 0; i < 2; i++) {
            int f  = i * 256 + tid;
            int kk = f >> 4;
            int d4 = (f & 15) << 2;
            *(float4*)(&Vs[kk][d4]) =
                *(const float4*)(g_vp + (size_t)(b * Sc + kt + kk) * DMc + h * DHc + d4);
        }
        __syncthreads();

#pragma unroll
        for (int k = 0; k < 32; k++) {
            float pf[8];
            *(float4*)(pf)     = *(const float4*)(&Ps[k][q0]);
            *(float4*)(pf + 4) = *(const float4*)(&Ps[k][q0 + 4]);
            float4 vf = *(const float4*)(&Vs[k][d0]);
#pragma unroll
            for (int i = 0; i < 8; i++) {
                acc[i][0] = fmaf(pf[i], vf.x, acc[i][0]);
                acc[i][1] = fmaf(pf[i], vf.y, acc[i][1]);
                acc[i][2] = fmaf(pf[i], vf.z, acc[i][2]);
                acc[i][3] = fmaf(pf[i], vf.w, acc[i][3]);
            }
        }
        __syncthreads();
    }

#pragma unroll
    for (int i = 0; i < 8; i++) {
        int q = qb + q0 + i;
        float4 o = make_float4(acc[i][0], acc[i][1], acc[i][2], acc[i][3]);
        *(float4*)(g_outpre + (size_t)(b * Sc + q) * DMc + h * DHc + d0) = o;
    }
}

// K6: final projection out_pre @ Wo + bo -> d_out[0 : B*S*DM]
__global__ __launch_bounds__(256)
void out_kernel(const float* __restrict__ Wo, const float* __restrict__ bo,
                float* __restrict__ out)
{
    sgemm128(g_outpre, Wo, bo, out, DMc, DMc);
}

extern "C" void kernel_launch(void* const* d_in, const int* in_sizes, int n_in,
                              void* d_out, int out_size)
{
    const float* q     = (const float*)d_in[0];
    const float* k     = (const float*)d_in[1];
    const float* v     = (const float*)d_in[2];
    const float* xdiff = (const float*)d_in[3];
    const int*   mask  = (const int*)d_in[4];
    const float* Wq = (const float*)d_in[5];
    const float* bq = (const float*)d_in[6];
    const float* Wk = (const float*)d_in[7];
    const float* bk = (const float*)d_in[8];
    const float* Wv = (const float*)d_in[9];
    const float* bv = (const float*)d_in[10];
    const float* Wa = (const float*)d_in[11];
    const float* ba = (const float*)d_in[12];
    const float* Wb = (const float*)d_in[13];
    const float* bb = (const float*)d_in[14];
    const float* Wo = (const float*)d_in[15];
    const float* bo = (const float*)d_in[16];

    float* out  = (float*)d_out;                 // (B,S,DM)
    float* attn = out + (size_t)Bc * Sc * DMc;   // (B,H,S,S) follows

    dim3 blk(16, 16);

    proj_kernel<<<dim3(DMc / 128, Mrows / 128, 3), blk>>>(q, k, v, Wq, Wk, Wv, bq, bk, bv);
    ab_kernel<<<Mrows / 8, 256>>>(Wa, ba, Wb, bb);
    logits_kernel<<<dim3(Sc / 128, Sc / 128, BHc), blk>>>(xdiff, mask, attn);
    stats_kernel<<<BHc * Sc, 256>>>(attn);
    attnv_kernel<<<dim3(Sc / 128, BHc), blk>>>(attn);
    out_kernel<<<dim3(DMc / 128, Mrows / 128), blk>>>(Wo, bo, out);
}

// round 6
// speedup vs baseline: 1.3952x; 1.3952x over previous
#include <cuda_runtime.h>
#include <cuda_bf16.h>
#include <cstdint>

// Shapes (fixed by the problem)
static constexpr int Bc  = 2;
static constexpr int Sc  = 2048;
static constexpr int DMc = 512;
static constexpr int Hc  = 8;
static constexpr int DHc = 64;
static constexpr int BHc = Bc * Hc;          // 16
static constexpr int Mrows = Bc * Sc;        // 4096

// -------- device scratch (no allocations allowed) --------
__device__ float g_qp[Mrows * DMc];
__device__ float g_kp[Mrows * DMc];
__device__ float g_vp[Mrows * DMc];
__device__ float g_outpre[Mrows * DMc];
__device__ float g_a[BHc * Sc];
__device__ float g_b[BHc * Sc];
__device__ float g_rmax[BHc * Sc];
__device__ float g_rinv[BHc * Sc];

// ==================== warp-mma helpers (sm_80+ path, valid on sm_103) ====================
__device__ __forceinline__ uint32_t smem_u32(const void* p) {
    uint32_t a;
    asm("{ .reg .u64 t; cvta.to.shared.u64 t, %1; cvt.u32.u64 %0, t; }" : "=r"(a) : "l"(p));
    return a;
}

__device__ __forceinline__ void ldsm4(uint32_t (&r)[4], uint32_t addr) {
    asm volatile("ldmatrix.sync.aligned.m8n8.x4.shared.b16 {%0,%1,%2,%3}, [%4];"
        : "=r"(r[0]), "=r"(r[1]), "=r"(r[2]), "=r"(r[3]) : "r"(addr));
}

__device__ __forceinline__ void mma16816(float (&c)[4], const uint32_t (&a)[4],
                                         uint32_t b0, uint32_t b1) {
    asm volatile(
        "mma.sync.aligned.m16n8k16.row.col.f32.bf16.bf16.f32 "
        "{%0,%1,%2,%3}, {%4,%5,%6,%7}, {%8,%9}, {%0,%1,%2,%3};"
        : "+f"(c[0]), "+f"(c[1]), "+f"(c[2]), "+f"(c[3])
        : "r"(a[0]), "r"(a[1]), "r"(a[2]), "r"(a[3]), "r"(b0), "r"(b1));
}

// A-operand x4 ldmatrix address: rows r0+ (lane&15), k halves by lane>>4.
// base = smem byte addr of buffer; stride in u32 words; k0 in b16 elements.
__device__ __forceinline__ uint32_t addrA(uint32_t base, int r0, int k0, int lane, int stride) {
    return base + (uint32_t)(((r0 + (lane & 15)) * stride + (k0 >> 1) + (lane >> 4) * 4) * 4);
}
// B-operand x4 ldmatrix address: two n8 blocks (rows n0..n0+15), k halves.
__device__ __forceinline__ uint32_t addrB(uint32_t base, int n0, int k0, int lane, int stride) {
    int r = n0 + (lane & 7) + ((lane >> 4) & 1) * 8;
    int c = (k0 >> 1) + ((lane >> 3) & 1) * 4;
    return base + (uint32_t)((r * stride + c) * 4);
}

// split fp32 pair -> packed bf16 hi pair and lo pair (low half = lower-k element)
__device__ __forceinline__ void split2(float x0, float x1, uint32_t& hi, uint32_t& lo) {
    __nv_bfloat16 h0 = __float2bfloat16(x0), h1 = __float2bfloat16(x1);
    float r0 = x0 - __bfloat162float(h0), r1 = x1 - __bfloat162float(h1);
    __nv_bfloat16 l0 = __float2bfloat16(r0), l1 = __float2bfloat16(r1);
    hi = (uint32_t)__bfloat16_as_ushort(h0) | ((uint32_t)__bfloat16_as_ushort(h1) << 16);
    lo = (uint32_t)__bfloat16_as_ushort(l0) | ((uint32_t)__bfloat16_as_ushort(l1) << 16);
}

// ============================================================
// K1: HMMA GEMM  C[M,512] = A[M,512] @ W[512,512] + bias  (split precision)
// grid = (4 ntile, M/128), block = 256 (8 warps: 4 m x 2 n), warp tile 32x64
// ============================================================
__global__ __launch_bounds__(256, 1)
void gemm_tc_kernel(const float* __restrict__ A, const float* __restrict__ W,
                    const float* __restrict__ bias, float* __restrict__ C)
{
    // SMEM: As hi/lo [128][20] u32, Bs hi/lo [128][20] u32  (stride 20 words = 80B)
    __shared__ uint32_t sm[4 * 128 * 20];
    const int ASH = 0, ASL = 2560, BSH = 5120, BSL = 7680, RS = 20;

    const int tid = threadIdx.x;
    const int w = tid >> 5, lane = tid & 31;
    const int g = lane >> 2, t = lane & 3;
    const int mb = blockIdx.y * 128, nb = blockIdx.x * 128;
    const int wm = (w >> 1) * 32, wn = (w & 1) * 64;
    const uint32_t sbase = smem_u32(sm);

    float c[2][8][4];
#pragma unroll
    for (int mi = 0; mi < 2; mi++)
#pragma unroll
        for (int nf = 0; nf < 8; nf++)
#pragma unroll
            for (int r = 0; r < 4; r++) c[mi][nf][r] = 0.f;

    const int arow_i = tid >> 1, aseg = tid & 1;
    const float* arow = A + (size_t)(mb + arow_i) * DMc;
    const int bn = tid & 127, bkh = tid >> 7;

    for (int kc = 0; kc < 16; kc++) {
        // stage A chunk 128x32 (hi/lo)
#pragma unroll
        for (int i = 0; i < 4; i++) {
            int f4 = aseg * 4 + i;
            float4 v = *(const float4*)(arow + kc * 32 + f4 * 4);
            uint32_t h0, l0, h1, l1;
            split2(v.x, v.y, h0, l0);
            split2(v.z, v.w, h1, l1);
            sm[ASH + arow_i * RS + f4 * 2]     = h0;
            sm[ASH + arow_i * RS + f4 * 2 + 1] = h1;
            sm[ASL + arow_i * RS + f4 * 2]     = l0;
            sm[ASL + arow_i * RS + f4 * 2 + 1] = l1;
        }
        // stage W^T chunk: Bs[n][kp] from W[k][n]
#pragma unroll
        for (int i = 0; i < 8; i++) {
            int kp = bkh * 8 + i;
            const float* wp = W + (size_t)(kc * 32 + 2 * kp) * DMc + nb + bn;
            float w0 = wp[0], w1 = wp[DMc];
            uint32_t hi, lo;
            split2(w0, w1, hi, lo);
            sm[BSH + bn * RS + kp] = hi;
            sm[BSL + bn * RS + kp] = lo;
        }
        __syncthreads();

#pragma unroll
        for (int kk = 0; kk < 2; kk++) {
            uint32_t ah[2][4], al[2][4];
#pragma unroll
            for (int mi = 0; mi < 2; mi++) {
                ldsm4(ah[mi], addrA(sbase + ASH * 4, wm + mi * 16, kk * 16, lane, RS));
                ldsm4(al[mi], addrA(sbase + ASL * 4, wm + mi * 16, kk * 16, lane, RS));
            }
#pragma unroll
            for (int nb2 = 0; nb2 < 4; nb2++) {
                uint32_t bhf[4], blf[4];
                ldsm4(bhf, addrB(sbase + BSH * 4, wn + nb2 * 16, kk * 16, lane, RS));
                ldsm4(blf, addrB(sbase + BSL * 4, wn + nb2 * 16, kk * 16, lane, RS));
#pragma unroll
                for (int mi = 0; mi < 2; mi++) {
                    mma16816(c[mi][2 * nb2],     ah[mi], bhf[0], bhf[1]);
                    mma16816(c[mi][2 * nb2],     ah[mi], blf[0], blf[1]);
                    mma16816(c[mi][2 * nb2],     al[mi], bhf[0], bhf[1]);
                    mma16816(c[mi][2 * nb2 + 1], ah[mi], bhf[2], bhf[3]);
                    mma16816(c[mi][2 * nb2 + 1], ah[mi], blf[2], blf[3]);
                    mma16816(c[mi][2 * nb2 + 1], al[mi], bhf[2], bhf[3]);
                }
            }
        }
        __syncthreads();
    }

    // epilogue
#pragma unroll
    for (int mi = 0; mi < 2; mi++)
#pragma unroll
        for (int hh = 0; hh < 2; hh++) {
            int row = mb + wm + mi * 16 + hh * 8 + g;
#pragma unroll
            for (int nf = 0; nf < 8; nf++) {
                int col = nb + wn + nf * 8 + 2 * t;
                float2 bv = *(const float2*)(bias + col);
                float2 o;
                o.x = c[mi][nf][hh * 2 + 0] + bv.x;
                o.y = c[mi][nf][hh * 2 + 1] + bv.y;
                *(float2*)(C + (size_t)row * DMc + col) = o;
            }
        }
}

// ============================================================
// K2: a,b heads. grid = 512, block = 256.
// ============================================================
__global__ __launch_bounds__(256)
void ab_kernel(const float* __restrict__ Wa, const float* __restrict__ ba,
               const float* __restrict__ Wb, const float* __restrict__ bb)
{
    const int warp = threadIdx.x >> 5;
    const int lane = threadIdx.x & 31;
    const int row  = blockIdx.x * 8 + warp;
    const int b    = row / Sc;
    const int s    = row - b * Sc;

    float acca[8], accb[8];
#pragma unroll
    for (int h = 0; h < 8; h++) { acca[h] = 0.f; accb[h] = 0.f; }
    for (int t = 0; t < DMc / 32; t++) {
        int d = lane + t * 32;
        float x = g_qp[(size_t)row * DMc + d];
#pragma unroll
        for (int h = 0; h < 8; h++) {
            acca[h] = fmaf(x, Wa[d * Hc + h], acca[h]);
            accb[h] = fmaf(x, Wb[d * Hc + h], accb[h]);
        }
    }
#pragma unroll
    for (int h = 0; h < 8; h++) {
#pragma unroll
        for (int o = 16; o > 0; o >>= 1) {
            acca[h] += __shfl_down_sync(0xffffffff, acca[h], o);
            accb[h] += __shfl_down_sync(0xffffffff, accb[h], o);
        }
    }
    if (lane == 0) {
#pragma unroll
        for (int h = 0; h < 8; h++) {
            g_a[(b * Hc + h) * Sc + s] = acca[h] + ba[h];
            g_b[(b * Hc + h) * Sc + s] = accb[h] + bb[h];
        }
    }
}

// Shared smem layout for stats/attnv kernels (dynamic, 73728 B):
// QH [128][36] u32, QL, KVH, KVL
static constexpr int QH_O = 0, QL_O = 4608, KVH_O = 9216, KVL_O = 13824;
static constexpr int RSQ = 36;   // 144B rows (Q/K)
static constexpr int RSV = 68;   // 272B rows (V^T)
static constexpr int DYN_SMEM = 18432 * 4;

// stage 128 rows x 64 d (hi/lo) from src rows base_row.. into sm[offH/offL], stride 36
__device__ __forceinline__ void stage_qk(uint32_t* sm, int offH, int offL,
                                         const float* __restrict__ src, int tid)
{
    int row = tid >> 1, seg = tid & 1;
    const float* r = src + (size_t)row * DMc;
#pragma unroll
    for (int i = 0; i < 8; i++) {
        int f4 = seg * 8 + i;
        float4 v = *(const float4*)(r + f4 * 4);
        uint32_t h0, l0, h1, l1;
        split2(v.x, v.y, h0, l0);
        split2(v.z, v.w, h1, l1);
        sm[offH + row * RSQ + f4 * 2]     = h0;
        sm[offH + row * RSQ + f4 * 2 + 1] = h1;
        sm[offL + row * RSQ + f4 * 2]     = l0;
        sm[offL + row * RSQ + f4 * 2 + 1] = l1;
    }
}

// compute 128x128 score tile into c[2][8][4] (Q from QH/QL, K from KVH/KVL)
__device__ __forceinline__ void score_mma(float (&c)[2][8][4], uint32_t sbase,
                                          int wm, int wn, int lane)
{
#pragma unroll
    for (int mi = 0; mi < 2; mi++)
#pragma unroll
        for (int nf = 0; nf < 8; nf++)
#pragma unroll
            for (int r = 0; r < 4; r++) c[mi][nf][r] = 0.f;
#pragma unroll
    for (int kk = 0; kk < 4; kk++) {
        uint32_t ah[2][4], al[2][4];
#pragma unroll
        for (int mi = 0; mi < 2; mi++) {
            ldsm4(ah[mi], addrA(sbase + QH_O * 4, wm + mi * 16, kk * 16, lane, RSQ));
            ldsm4(al[mi], addrA(sbase + QL_O * 4, wm + mi * 16, kk * 16, lane, RSQ));
        }
#pragma unroll
        for (int nb2 = 0; nb2 < 4; nb2++) {
            uint32_t bhf[4], blf[4];
            ldsm4(bhf, addrB(sbase + KVH_O * 4, wn + nb2 * 16, kk * 16, lane, RSQ));
            ldsm4(blf, addrB(sbase + KVL_O * 4, wn + nb2 * 16, kk * 16, lane, RSQ));
#pragma unroll
            for (int mi = 0; mi < 2; mi++) {
                mma16816(c[mi][2 * nb2],     ah[mi], bhf[0], bhf[1]);
                mma16816(c[mi][2 * nb2],     ah[mi], blf[0], blf[1]);
                mma16816(c[mi][2 * nb2],     al[mi], bhf[0], bhf[1]);
                mma16816(c[mi][2 * nb2 + 1], ah[mi], bhf[2], bhf[3]);
                mma16816(c[mi][2 * nb2 + 1], ah[mi], blf[2], blf[3]);
                mma16816(c[mi][2 * nb2 + 1], al[mi], bhf[2], bhf[3]);
            }
        }
    }
}

// ============================================================
// K3: stats — score tiles + full logit epilogue + online max/sum.
// grid = (16 qtile, 16 bh), block = 256.
// ============================================================
__global__ __launch_bounds__(256, 1)
void stats_tc_kernel(const float* __restrict__ xdiff, const int* __restrict__ mask)
{
    extern __shared__ uint32_t sm[];
    const int tid = threadIdx.x, w = tid >> 5, lane = tid & 31;
    const int g = lane >> 2, t = lane & 3;
    const int bh = blockIdx.y, b = bh >> 3, h = bh & 7;
    const int qb = blockIdx.x * 128;
    const int wm = (w >> 1) * 32, wn = (w & 1) * 64;
    const uint32_t sbase = smem_u32(sm);

    stage_qk(sm, QH_O, QL_O, g_qp + (size_t)(b * Sc + qb) * DMc + h * DHc, tid);
    __syncthreads();

    float rm[4], rs[4];
    float aqv[4], bqv[4];
    const float* xr[4];
#pragma unroll
    for (int mi = 0; mi < 2; mi++)
#pragma unroll
        for (int hh = 0; hh < 2; hh++) {
            int idx = mi * 2 + hh;
            int q = qb + wm + mi * 16 + hh * 8 + g;
            rm[idx] = -3.0e38f; rs[idx] = 0.f;
            aqv[idx] = g_a[bh * Sc + q];
            bqv[idx] = g_b[bh * Sc + q];
            xr[idx] = xdiff + ((size_t)b * Sc + q) * Sc;
        }
    const int* mrow = mask + b * Sc;

    for (int kt = 0; kt < 16; kt++) {
        const int kb = kt * 128;
        stage_qk(sm, KVH_O, KVL_O, g_kp + (size_t)(b * Sc + kb) * DMc + h * DHc, tid);
        __syncthreads();

        float c[2][8][4];
        score_mma(c, sbase, wm, wn, lane);
        __syncthreads();   // all ldmatrix reads done before next stage overwrite

#pragma unroll
        for (int mi = 0; mi < 2; mi++)
#pragma unroll
            for (int nf = 0; nf < 8; nf++) {
                int col = kb + wn + nf * 8 + 2 * t;
                int2 mv = *(const int2*)(mrow + col);
                float mt0 = (float)mv.x * -1e9f, mt1 = (float)mv.y * -1e9f;
#pragma unroll
                for (int hh = 0; hh < 2; hh++) {
                    int idx = mi * 2 + hh;
                    float2 xd = *(const float2*)(xr[idx] + col);
                    float l0 = c[mi][nf][hh * 2 + 0] * 0.125f + mt0 + aqv[idx] * xd.x + bqv[idx] * xd.x * xd.x;
                    float l1 = c[mi][nf][hh * 2 + 1] * 0.125f + mt1 + aqv[idx] * xd.y + bqv[idx] * xd.y * xd.y;
                    float mx = fmaxf(l0, l1);
                    if (mx > rm[idx]) { rs[idx] *= __expf(rm[idx] - mx); rm[idx] = mx; }
                    rs[idx] += __expf(l0 - rm[idx]) + __expf(l1 - rm[idx]);
                }
            }
    }

    // quad reduce (lanes sharing same rows)
#pragma unroll
    for (int off = 1; off <= 2; off <<= 1)
#pragma unroll
        for (int i = 0; i < 4; i++) {
            float om = __shfl_xor_sync(0xffffffff, rm[i], off);
            float os = __shfl_xor_sync(0xffffffff, rs[i], off);
            float nm = fmaxf(rm[i], om);
            rs[i] = rs[i] * __expf(rm[i] - nm) + os * __expf(om - nm);
            rm[i] = nm;
        }

    // cross warp-pair merge via smem
    __syncthreads();
    float2* red = (float2*)sm;           // 8 warps * 32 rows
    if (t == 0) {
#pragma unroll
        for (int i = 0; i < 4; i++) {
            int rl = (i >> 1) * 16 + (i & 1) * 8 + g;   // mi*16 + hh*8 + g
            red[w * 32 + rl] = make_float2(rm[i], rs[i]);
        }
    }
    __syncthreads();
    if (!(w & 1) && t == 0) {
#pragma unroll
        for (int i = 0; i < 4; i++) {
            int rl = (i >> 1) * 16 + (i & 1) * 8 + g;
            float2 p = red[(w ^ 1) * 32 + rl];
            float nm = fmaxf(rm[i], p.x);
            float ns = rs[i] * __expf(rm[i] - nm) + p.y * __expf(p.x - nm);
            int q = qb + wm + rl;
            g_rmax[bh * Sc + q] = nm;
            g_rinv[bh * Sc + q] = 1.0f / ns;
        }
    }
}

// ============================================================
// K4: attnV — recompute scores, normalize, write attn, P@V via frag reuse.
// grid = (16 qtile, 16 bh), block = 256.
// ============================================================
__global__ __launch_bounds__(256, 1)
void attnv_tc_kernel(const float* __restrict__ xdiff, const int* __restrict__ mask,
                     float* __restrict__ attn)
{
    extern __shared__ uint32_t sm[];
    const int tid = threadIdx.x, w = tid >> 5, lane = tid & 31;
    const int g = lane >> 2, t = lane & 3;
    const int bh = blockIdx.y, b = bh >> 3, h = bh & 7;
    const int qb = blockIdx.x * 128;
    const int wm = (w >> 1) * 32, wn = (w & 1) * 64;
    const uint32_t sbase = smem_u32(sm);

    stage_qk(sm, QH_O, QL_O, g_qp + (size_t)(b * Sc + qb) * DMc + h * DHc, tid);
    __syncthreads();

    float aqv[4], bqv[4], msv[4], invv[4];
    const float* xr[4];
    float* arow[4];
#pragma unroll
    for (int mi = 0; mi < 2; mi++)
#pragma unroll
        for (int hh = 0; hh < 2; hh++) {
            int idx = mi * 2 + hh;
            int q = qb + wm + mi * 16 + hh * 8 + g;
            aqv[idx] = g_a[bh * Sc + q];
            bqv[idx] = g_b[bh * Sc + q];
            msv[idx] = g_rmax[bh * Sc + q];
            invv[idx] = g_rinv[bh * Sc + q];
            xr[idx] = xdiff + ((size_t)b * Sc + q) * Sc;
            arow[idx] = attn + ((size_t)bh * Sc + q) * Sc;
        }
    const int* mrow = mask + b * Sc;

    float o[2][8][4];
#pragma unroll
    for (int mi = 0; mi < 2; mi++)
#pragma unroll
        for (int nf = 0; nf < 8; nf++)
#pragma unroll
            for (int r = 0; r < 4; r++) o[mi][nf][r] = 0.f;

    const int vd = tid & 63, vkq = tid >> 6;

    for (int kt = 0; kt < 16; kt++) {
        const int kb = kt * 128;
        // stage K
        stage_qk(sm, KVH_O, KVL_O, g_kp + (size_t)(b * Sc + kb) * DMc + h * DHc, tid);
        __syncthreads();

        float c[2][8][4];
        score_mma(c, sbase, wm, wn, lane);
        __syncthreads();   // K smem reads complete

        // stage V^T (64 d rows x 64 k-pairs), stride 68, same buffer
#pragma unroll
        for (int i = 0; i < 16; i++) {
            int kp = vkq * 16 + i;
            const float* vb = g_vp + (size_t)(b * Sc + kb + 2 * kp) * DMc + h * DHc + vd;
            float v0 = vb[0], v1 = vb[DMc];
            uint32_t hi, lo;
            split2(v0, v1, hi, lo);
            sm[KVH_O + vd * RSV + kp] = hi;
            sm[KVL_O + vd * RSV + kp] = lo;
        }
        __syncthreads();

        // per k16 group: softmax epilogue + direct P@V
#pragma unroll
        for (int j = 0; j < 4; j++) {
            uint32_t pah[2][4], pal[2][4];
#pragma unroll
            for (int mi = 0; mi < 2; mi++)
#pragma unroll
                for (int nn = 0; nn < 2; nn++) {
                    int nf = 2 * j + nn;
                    int col = kb + wn + nf * 8 + 2 * t;
                    int2 mv = *(const int2*)(mrow + col);
                    float mt0 = (float)mv.x * -1e9f, mt1 = (float)mv.y * -1e9f;
#pragma unroll
                    for (int hh = 0; hh < 2; hh++) {
                        int idx = mi * 2 + hh;
                        float2 xd = *(const float2*)(xr[idx] + col);
                        float l0 = c[mi][nf][hh * 2 + 0] * 0.125f + mt0 + aqv[idx] * xd.x + bqv[idx] * xd.x * xd.x;
                        float l1 = c[mi][nf][hh * 2 + 1] * 0.125f + mt1 + aqv[idx] * xd.y + bqv[idx] * xd.y * xd.y;
                        float p0 = __expf(l0 - msv[idx]) * invv[idx];
                        float p1 = __expf(l1 - msv[idx]) * invv[idx];
                        *(float2*)(arow[idx] + col) = make_float2(p0, p1);
                        split2(p0, p1, pah[mi][nn * 2 + hh], pal[mi][nn * 2 + hh]);
                    }
                }
#pragma unroll
            for (int nd = 0; nd < 4; nd++) {
                uint32_t vh[4], vl[4];
                ldsm4(vh, addrB(sbase + KVH_O * 4, nd * 16, wn + j * 16, lane, RSV));
                ldsm4(vl, addrB(sbase + KVL_O * 4, nd * 16, wn + j * 16, lane, RSV));
#pragma unroll
                for (int mi = 0; mi < 2; mi++) {
                    mma16816(o[mi][2 * nd],     pah[mi], vh[0], vh[1]);
                    mma16816(o[mi][2 * nd],     pah[mi], vl[0], vl[1]);
                    mma16816(o[mi][2 * nd],     pal[mi], vh[0], vh[1]);
                    mma16816(o[mi][2 * nd + 1], pah[mi], vh[2], vh[3]);
                    mma16816(o[mi][2 * nd + 1], pah[mi], vl[2], vl[3]);
                    mma16816(o[mi][2 * nd + 1], pal[mi], vh[2], vh[3]);
                }
            }
        }
        __syncthreads();   // V smem reads complete before next K stage
    }

    // reduce out across the warp pair (two key halves), padded stride 65
    float* red = (float*)(sm + KVH_O);
    if (w & 1) {
        float* dst = red + ((w >> 1) * 32 + lane) * 65;
#pragma unroll
        for (int mi = 0; mi < 2; mi++)
#pragma unroll
            for (int nf = 0; nf < 8; nf++)
#pragma unroll
                for (int r = 0; r < 4; r++)
                    dst[mi * 32 + nf * 4 + r] = o[mi][nf][r];
    }
    __syncthreads();
    if (!(w & 1)) {
        const float* src = red + ((w >> 1) * 32 + lane) * 65;
#pragma unroll
        for (int mi = 0; mi < 2; mi++)
#pragma unroll
            for (int nf = 0; nf < 8; nf++)
#pragma unroll
                for (int r = 0; r < 4; r++)
                    o[mi][nf][r] += src[mi * 32 + nf * 4 + r];
#pragma unroll
        for (int mi = 0; mi < 2; mi++)
#pragma unroll
            for (int hh = 0; hh < 2; hh++) {
                int q = qb + wm + mi * 16 + hh * 8 + g;
#pragma unroll
                for (int nf = 0; nf < 8; nf++) {
                    float2 val = make_float2(o[mi][nf][hh * 2 + 0], o[mi][nf][hh * 2 + 1]);
                    *(float2*)(g_outpre + (size_t)(b * Sc + q) * DMc + h * DHc + nf * 8 + 2 * t) = val;
                }
            }
    }
}

// ============================================================
extern "C" void kernel_launch(void* const* d_in, const int* in_sizes, int n_in,
                              void* d_out, int out_size)
{
    const float* q     = (const float*)d_in[0];
    const float* k     = (const float*)d_in[1];
    const float* v     = (const float*)d_in[2];
    const float* xdiff = (const float*)d_in[3];
    const int*   mask  = (const int*)d_in[4];
    const float* Wq = (const float*)d_in[5];
    const float* bq = (const float*)d_in[6];
    const float* Wk = (const float*)d_in[7];
    const float* bk = (const float*)d_in[8];
    const float* Wv = (const float*)d_in[9];
    const float* bv = (const float*)d_in[10];
    const float* Wa = (const float*)d_in[11];
    const float* ba = (const float*)d_in[12];
    const float* Wb = (const float*)d_in[13];
    const float* bb = (const float*)d_in[14];
    const float* Wo = (const float*)d_in[15];
    const float* bo = (const float*)d_in[16];

    float* out  = (float*)d_out;                 // (B,S,DM)
    float* attn = out + (size_t)Bc * Sc * DMc;   // (B,H,S,S)

    float *d_qp = nullptr, *d_kp = nullptr, *d_vp = nullptr, *d_op = nullptr;
    cudaGetSymbolAddress((void**)&d_qp, g_qp);
    cudaGetSymbolAddress((void**)&d_kp, g_kp);
    cudaGetSymbolAddress((void**)&d_vp, g_vp);
    cudaGetSymbolAddress((void**)&d_op, g_outpre);

    cudaFuncSetAttribute(stats_tc_kernel, cudaFuncAttributeMaxDynamicSharedMemorySize, DYN_SMEM);
    cudaFuncSetAttribute(attnv_tc_kernel, cudaFuncAttributeMaxDynamicSharedMemorySize, DYN_SMEM);

    dim3 gp(DMc / 128, Mrows / 128);
    gemm_tc_kernel<<<gp, 256>>>(q, Wq, bq, d_qp);
    gemm_tc_kernel<<<gp, 256>>>(k, Wk, bk, d_kp);
    gemm_tc_kernel<<<gp, 256>>>(v, Wv, bv, d_vp);
    ab_kernel<<<Mrows / 8, 256>>>(Wa, ba, Wb, bb);
    stats_tc_kernel<<<dim3(Sc / 128, BHc), 256, DYN_SMEM>>>(xdiff, mask);
    attnv_tc_kernel<<<dim3(Sc / 128, BHc), 256, DYN_SMEM>>>(xdiff, mask, attn);
    gemm_tc_kernel<<<gp, 256>>>(d_op, Wo, bo, out);
}

// round 7
// speedup vs baseline: 1.5331x; 1.0988x over previous
#include <cuda_runtime.h>
#include <cuda_bf16.h>
#include <cstdint>

// Shapes (fixed by the problem)
static constexpr int Bc  = 2;
static constexpr int Sc  = 2048;
static constexpr int DMc = 512;
static constexpr int Hc  = 8;
static constexpr int DHc = 64;
static constexpr int BHc = Bc * Hc;          // 16
static constexpr int Mrows = Bc * Sc;        // 4096

// -------- device scratch (no allocations allowed) --------
__device__ float g_qp[Mrows * DMc];          // fp32 qp (for ab_kernel)
__device__ float g_outpre[Mrows * DMc];
__device__ float g_a[BHc * Sc];
__device__ float g_b[BHc * Sc];
__device__ float g_rmax[BHc * Sc];
__device__ float g_rinv[BHc * Sc];
// prepacked bf16 hi/lo: Q,K row-major packed 2-per-u32; V transposed per head
__device__ __align__(16) uint32_t g_qph[Mrows * DMc / 2];
__device__ __align__(16) uint32_t g_qpl[Mrows * DMc / 2];
__device__ __align__(16) uint32_t g_kph[Mrows * DMc / 2];
__device__ __align__(16) uint32_t g_kpl[Mrows * DMc / 2];
__device__ __align__(16) __nv_bfloat16 g_vth[Mrows * DMc];   // [bh][d][s]
__device__ __align__(16) __nv_bfloat16 g_vtl[Mrows * DMc];

// ==================== warp-mma helpers ====================
__device__ __forceinline__ uint32_t smem_u32(const void* p) {
    uint32_t a;
    asm("{ .reg .u64 t; cvta.to.shared.u64 t, %1; cvt.u32.u64 %0, t; }" : "=r"(a) : "l"(p));
    return a;
}
__device__ __forceinline__ void ldsm4(uint32_t (&r)[4], uint32_t addr) {
    asm volatile("ldmatrix.sync.aligned.m8n8.x4.shared.b16 {%0,%1,%2,%3}, [%4];"
        : "=r"(r[0]), "=r"(r[1]), "=r"(r[2]), "=r"(r[3]) : "r"(addr));
}
__device__ __forceinline__ void mma16816(float (&c)[4], const uint32_t (&a)[4],
                                         uint32_t b0, uint32_t b1) {
    asm volatile(
        "mma.sync.aligned.m16n8k16.row.col.f32.bf16.bf16.f32 "
        "{%0,%1,%2,%3}, {%4,%5,%6,%7}, {%8,%9}, {%0,%1,%2,%3};"
        : "+f"(c[0]), "+f"(c[1]), "+f"(c[2]), "+f"(c[3])
        : "r"(a[0]), "r"(a[1]), "r"(a[2]), "r"(a[3]), "r"(b0), "r"(b1));
}
__device__ __forceinline__ uint32_t addrA(uint32_t base, int r0, int k0, int lane, int stride) {
    return base + (uint32_t)(((r0 + (lane & 15)) * stride + (k0 >> 1) + (lane >> 4) * 4) * 4);
}
__device__ __forceinline__ uint32_t addrB(uint32_t base, int n0, int k0, int lane, int stride) {
    int r = n0 + (lane & 7) + ((lane >> 4) & 1) * 8;
    int c = (k0 >> 1) + ((lane >> 3) & 1) * 4;
    return base + (uint32_t)((r * stride + c) * 4);
}
__device__ __forceinline__ void split2(float x0, float x1, uint32_t& hi, uint32_t& lo) {
    __nv_bfloat16 h0 = __float2bfloat16(x0), h1 = __float2bfloat16(x1);
    float r0 = x0 - __bfloat162float(h0), r1 = x1 - __bfloat162float(h1);
    __nv_bfloat16 l0 = __float2bfloat16(r0), l1 = __float2bfloat16(r1);
    hi = (uint32_t)__bfloat16_as_ushort(h0) | ((uint32_t)__bfloat16_as_ushort(h1) << 16);
    lo = (uint32_t)__bfloat16_as_ushort(l0) | ((uint32_t)__bfloat16_as_ushort(l1) << 16);
}

// ============================================================
// GEMM body: C[M,512] = A[M,512] @ W[512,512] + bias  (split precision)
// block 256 (8 warps: 4 m x 2 n), tile 128x128, warp tile 32x64
// ============================================================
__device__ __forceinline__ void gemm_body(
    const float* __restrict__ A, const float* __restrict__ W,
    const float* __restrict__ bias,
    float* __restrict__ C, uint32_t* __restrict__ Hp, uint32_t* __restrict__ Lp,
    __nv_bfloat16* __restrict__ Ht, __nv_bfloat16* __restrict__ Lt,
    bool writeF, bool writeP, bool writeT, int mb, int nb)
{
    __shared__ uint32_t sm[4 * 128 * 20];
    const int ASH = 0, ASL = 2560, BSH = 5120, BSL = 7680, RS = 20;

    const int tid = threadIdx.x;
    const int w = tid >> 5, lane = tid & 31;
    const int g = lane >> 2, t = lane & 3;
    const int wm = (w >> 1) * 32, wn = (w & 1) * 64;
    const uint32_t sbase = smem_u32(sm);

    float c[2][8][4];
#pragma unroll
    for (int mi = 0; mi < 2; mi++)
#pragma unroll
        for (int nf = 0; nf < 8; nf++)
#pragma unroll
            for (int r = 0; r < 4; r++) c[mi][nf][r] = 0.f;

    const int arow_i = tid >> 1, aseg = tid & 1;
    const float* arow = A + (size_t)(mb + arow_i) * DMc;
    const int bn = tid & 127, bkh = tid >> 7;

    for (int kc = 0; kc < 16; kc++) {
#pragma unroll
        for (int i = 0; i < 4; i++) {
            int f4 = aseg * 4 + i;
            float4 v = *(const float4*)(arow + kc * 32 + f4 * 4);
            uint32_t h0, l0, h1, l1;
            split2(v.x, v.y, h0, l0);
            split2(v.z, v.w, h1, l1);
            sm[ASH + arow_i * RS + f4 * 2]     = h0;
            sm[ASH + arow_i * RS + f4 * 2 + 1] = h1;
            sm[ASL + arow_i * RS + f4 * 2]     = l0;
            sm[ASL + arow_i * RS + f4 * 2 + 1] = l1;
        }
#pragma unroll
        for (int i = 0; i < 8; i++) {
            int kp = bkh * 8 + i;
            const float* wp = W + (size_t)(kc * 32 + 2 * kp) * DMc + nb + bn;
            float w0 = wp[0], w1 = wp[DMc];
            uint32_t hi, lo;
            split2(w0, w1, hi, lo);
            sm[BSH + bn * RS + kp] = hi;
            sm[BSL + bn * RS + kp] = lo;
        }
        __syncthreads();

#pragma unroll
        for (int kk = 0; kk < 2; kk++) {
            uint32_t ah[2][4], al[2][4];
#pragma unroll
            for (int mi = 0; mi < 2; mi++) {
                ldsm4(ah[mi], addrA(sbase + ASH * 4, wm + mi * 16, kk * 16, lane, RS));
                ldsm4(al[mi], addrA(sbase + ASL * 4, wm + mi * 16, kk * 16, lane, RS));
            }
#pragma unroll
            for (int nb2 = 0; nb2 < 4; nb2++) {
                uint32_t bhf[4], blf[4];
                ldsm4(bhf, addrB(sbase + BSH * 4, wn + nb2 * 16, kk * 16, lane, RS));
                ldsm4(blf, addrB(sbase + BSL * 4, wn + nb2 * 16, kk * 16, lane, RS));
#pragma unroll
                for (int mi = 0; mi < 2; mi++) {
                    mma16816(c[mi][2 * nb2],     ah[mi], bhf[0], bhf[1]);
                    mma16816(c[mi][2 * nb2],     ah[mi], blf[0], blf[1]);
                    mma16816(c[mi][2 * nb2],     al[mi], bhf[0], bhf[1]);
                    mma16816(c[mi][2 * nb2 + 1], ah[mi], bhf[2], bhf[3]);
                    mma16816(c[mi][2 * nb2 + 1], ah[mi], blf[2], blf[3]);
                    mma16816(c[mi][2 * nb2 + 1], al[mi], bhf[2], bhf[3]);
                }
            }
        }
        __syncthreads();
    }

#pragma unroll
    for (int mi = 0; mi < 2; mi++)
#pragma unroll
        for (int hh = 0; hh < 2; hh++) {
            int row = mb + wm + mi * 16 + hh * 8 + g;
#pragma unroll
            for (int nf = 0; nf < 8; nf++) {
                int col = nb + wn + nf * 8 + 2 * t;
                float2 bv = *(const float2*)(bias + col);
                float ox = c[mi][nf][hh * 2 + 0] + bv.x;
                float oy = c[mi][nf][hh * 2 + 1] + bv.y;
                if (writeF)
                    *(float2*)(C + (size_t)row * DMc + col) = make_float2(ox, oy);
                if (writeP) {
                    uint32_t hi, lo;
                    split2(ox, oy, hi, lo);
                    size_t pi = ((size_t)row * DMc + col) >> 1;
                    Hp[pi] = hi;
                    Lp[pi] = lo;
                }
                if (writeT) {
                    __nv_bfloat16 h0 = __float2bfloat16(ox);
                    __nv_bfloat16 l0 = __float2bfloat16(ox - __bfloat162float(h0));
                    __nv_bfloat16 h1 = __float2bfloat16(oy);
                    __nv_bfloat16 l1 = __float2bfloat16(oy - __bfloat162float(h1));
                    size_t i0 = ((size_t)(((row >> 11) * Hc + (col >> 6)) * DHc + (col & 63))) * Sc
                              + (row & (Sc - 1));
                    Ht[i0] = h0; Lt[i0] = l0;
                    Ht[i0 + Sc] = h1; Lt[i0 + Sc] = l1;
                }
            }
        }
}

// K1: fused Q/K/V projections. grid = (4, 32, 3), block 256.
__global__ __launch_bounds__(256, 1)
void qkv_kernel(const float* __restrict__ q, const float* __restrict__ k,
                const float* __restrict__ v,
                const float* __restrict__ Wq, const float* __restrict__ Wk,
                const float* __restrict__ Wv,
                const float* __restrict__ bq, const float* __restrict__ bk,
                const float* __restrict__ bv)
{
    const int mb = blockIdx.y * 128, nb = blockIdx.x * 128;
    if (blockIdx.z == 0)
        gemm_body(q, Wq, bq, g_qp, g_qph, g_qpl, nullptr, nullptr, true, true, false, mb, nb);
    else if (blockIdx.z == 1)
        gemm_body(k, Wk, bk, nullptr, g_kph, g_kpl, nullptr, nullptr, false, true, false, mb, nb);
    else
        gemm_body(v, Wv, bv, nullptr, nullptr, nullptr, g_vth, g_vtl, false, false, true, mb, nb);
}

// K5: final projection. grid = (4, 32), block 256.
__global__ __launch_bounds__(256, 1)
void out_kernel(const float* __restrict__ Wo, const float* __restrict__ bo,
                float* __restrict__ out)
{
    gemm_body(g_outpre, Wo, bo, out, nullptr, nullptr, nullptr, nullptr,
              true, false, false, blockIdx.y * 128, blockIdx.x * 128);
}

// ============================================================
// K2: a,b heads. grid = 128, block 256, warp handles 4 rows, W cached in smem.
// ============================================================
__global__ __launch_bounds__(256)
void ab_kernel(const float* __restrict__ Wa, const float* __restrict__ ba,
               const float* __restrict__ Wb, const float* __restrict__ bb)
{
    __shared__ float4 sWa[512][2];
    __shared__ float4 sWb[512][2];
    const int tid = threadIdx.x;
#pragma unroll
    for (int i = 0; i < 4; i++) {
        int idx = tid + i * 256;
        ((float4*)sWa)[idx] = ((const float4*)Wa)[idx];
        ((float4*)sWb)[idx] = ((const float4*)Wb)[idx];
    }
    __syncthreads();

    const int w = tid >> 5, lane = tid & 31;
    const int rbase = blockIdx.x * 32 + w * 4;

    float acc[4][16];
#pragma unroll
    for (int j = 0; j < 4; j++)
#pragma unroll
        for (int h = 0; h < 16; h++) acc[j][h] = 0.f;

#pragma unroll
    for (int tt = 0; tt < 4; tt++) {
        const int d0 = tt * 128 + lane * 4;
        float4 x[4];
#pragma unroll
        for (int j = 0; j < 4; j++)
            x[j] = *(const float4*)(g_qp + (size_t)(rbase + j) * DMc + d0);
#pragma unroll
        for (int dd = 0; dd < 4; dd++) {
            float4 wa0 = sWa[d0 + dd][0], wa1 = sWa[d0 + dd][1];
            float4 wb0 = sWb[d0 + dd][0], wb1 = sWb[d0 + dd][1];
#pragma unroll
            for (int j = 0; j < 4; j++) {
                float xv = (&x[j].x)[dd];
                acc[j][0]  = fmaf(xv, wa0.x, acc[j][0]);
                acc[j][1]  = fmaf(xv, wa0.y, acc[j][1]);
                acc[j][2]  = fmaf(xv, wa0.z, acc[j][2]);
                acc[j][3]  = fmaf(xv, wa0.w, acc[j][3]);
                acc[j][4]  = fmaf(xv, wa1.x, acc[j][4]);
                acc[j][5]  = fmaf(xv, wa1.y, acc[j][5]);
                acc[j][6]  = fmaf(xv, wa1.z, acc[j][6]);
                acc[j][7]  = fmaf(xv, wa1.w, acc[j][7]);
                acc[j][8]  = fmaf(xv, wb0.x, acc[j][8]);
                acc[j][9]  = fmaf(xv, wb0.y, acc[j][9]);
                acc[j][10] = fmaf(xv, wb0.z, acc[j][10]);
                acc[j][11] = fmaf(xv, wb0.w, acc[j][11]);
                acc[j][12] = fmaf(xv, wb1.x, acc[j][12]);
                acc[j][13] = fmaf(xv, wb1.y, acc[j][13]);
                acc[j][14] = fmaf(xv, wb1.z, acc[j][14]);
                acc[j][15] = fmaf(xv, wb1.w, acc[j][15]);
            }
        }
    }
#pragma unroll
    for (int o = 16; o > 0; o >>= 1)
#pragma unroll
        for (int j = 0; j < 4; j++)
#pragma unroll
            for (int h = 0; h < 16; h++)
                acc[j][h] += __shfl_xor_sync(0xffffffff, acc[j][h], o);

    if (lane < 4) {
        int row = rbase + lane;
        int b = row >> 11, s = row & (Sc - 1);
#pragma unroll
        for (int h = 0; h < 8; h++) {
            g_a[(b * Hc + h) * Sc + s] = acc[lane][h] + ba[h];
            g_b[(b * Hc + h) * Sc + s] = acc[lane][h + 8] + bb[h];
        }
    }
}

// Shared smem layout for stats kernel (dynamic, 73728 B)
static constexpr int QH_O = 0, QL_O = 4608, KVH_O = 9216, KVL_O = 13824;
static constexpr int RSQ = 36;
static constexpr int DYN_SMEM = 18432 * 4;

// copy 128 rows x 64 bf16 (32 u32) from packed global hi/lo into smem stride-36 rows
__device__ __forceinline__ void stage_copy(uint32_t* sm, int offH, int offL,
        const uint32_t* __restrict__ srcH, const uint32_t* __restrict__ srcL,
        size_t rowbase, int tid)
{
    const int row = tid >> 1, half = tid & 1;
    const size_t s0 = rowbase + (size_t)row * (DMc / 2) + half * 16;
    const uint4* sH = (const uint4*)(srcH + s0);
    const uint4* sL = (const uint4*)(srcL + s0);
    uint4* dH = (uint4*)(sm + offH + row * RSQ + half * 16);
    uint4* dL = (uint4*)(sm + offL + row * RSQ + half * 16);
#pragma unroll
    for (int i = 0; i < 4; i++) { dH[i] = sH[i]; dL[i] = sL[i]; }
}

__device__ __forceinline__ void score_mma(float (&c)[2][8][4], uint32_t sbase,
                                          int wm, int wn, int lane)
{
#pragma unroll
    for (int mi = 0; mi < 2; mi++)
#pragma unroll
        for (int nf = 0; nf < 8; nf++)
#pragma unroll
            for (int r = 0; r < 4; r++) c[mi][nf][r] = 0.f;
#pragma unroll
    for (int kk = 0; kk < 4; kk++) {
        uint32_t ah[2][4], al[2][4];
#pragma unroll
        for (int mi = 0; mi < 2; mi++) {
            ldsm4(ah[mi], addrA(sbase + QH_O * 4, wm + mi * 16, kk * 16, lane, RSQ));
            ldsm4(al[mi], addrA(sbase + QL_O * 4, wm + mi * 16, kk * 16, lane, RSQ));
        }
#pragma unroll
        for (int nb2 = 0; nb2 < 4; nb2++) {
            uint32_t bhf[4], blf[4];
            ldsm4(bhf, addrB(sbase + KVH_O * 4, wn + nb2 * 16, kk * 16, lane, RSQ));
            ldsm4(blf, addrB(sbase + KVL_O * 4, wn + nb2 * 16, kk * 16, lane, RSQ));
#pragma unroll
            for (int mi = 0; mi < 2; mi++) {
                mma16816(c[mi][2 * nb2],     ah[mi], bhf[0], bhf[1]);
                mma16816(c[mi][2 * nb2],     ah[mi], blf[0], blf[1]);
                mma16816(c[mi][2 * nb2],     al[mi], bhf[0], bhf[1]);
                mma16816(c[mi][2 * nb2 + 1], ah[mi], bhf[2], bhf[3]);
                mma16816(c[mi][2 * nb2 + 1], ah[mi], blf[2], blf[3]);
                mma16816(c[mi][2 * nb2 + 1], al[mi], bhf[2], bhf[3]);
            }
        }
    }
}

// ============================================================
// K3: stats — scores + full logit epilogue, WRITES raw logits, online max/sum.
// grid = (16 qtile, 16 bh), block = 256.
// ============================================================
__global__ __launch_bounds__(256, 1)
void stats_tc_kernel(const float* __restrict__ xdiff, const int* __restrict__ mask,
                     float* __restrict__ attn)
{
    extern __shared__ uint32_t sm[];
    const int tid = threadIdx.x, w = tid >> 5, lane = tid & 31;
    const int g = lane >> 2, t = lane & 3;
    const int bh = blockIdx.y, b = bh >> 3, h = bh & 7;
    const int qb = blockIdx.x * 128;
    const int wm = (w >> 1) * 32, wn = (w & 1) * 64;
    const uint32_t sbase = smem_u32(sm);

    stage_copy(sm, QH_O, QL_O, g_qph, g_qpl,
               (size_t)(b * Sc + qb) * (DMc / 2) + h * (DHc / 2), tid);
    __syncthreads();

    float rm[4], rs[4], aqv[4], bqv[4];
    const float* xr[4];
    float* lrow[4];
#pragma unroll
    for (int mi = 0; mi < 2; mi++)
#pragma unroll
        for (int hh = 0; hh < 2; hh++) {
            int idx = mi * 2 + hh;
            int q = qb + wm + mi * 16 + hh * 8 + g;
            rm[idx] = -3.0e38f; rs[idx] = 0.f;
            aqv[idx] = g_a[bh * Sc + q];
            bqv[idx] = g_b[bh * Sc + q];
            xr[idx] = xdiff + ((size_t)b * Sc + q) * Sc;
            lrow[idx] = attn + ((size_t)bh * Sc + q) * Sc;
        }
    const int* mrow = mask + b * Sc;

    for (int kt = 0; kt < 16; kt++) {
        const int kb = kt * 128;
        stage_copy(sm, KVH_O, KVL_O, g_kph, g_kpl,
                   (size_t)(b * Sc + kb) * (DMc / 2) + h * (DHc / 2), tid);
        __syncthreads();

        float c[2][8][4];
        score_mma(c, sbase, wm, wn, lane);
        __syncthreads();

#pragma unroll
        for (int mi = 0; mi < 2; mi++)
#pragma unroll
            for (int nf = 0; nf < 8; nf++) {
                int col = kb + wn + nf * 8 + 2 * t;
                int2 mv = *(const int2*)(mrow + col);
                float mt0 = (float)mv.x * -1e9f, mt1 = (float)mv.y * -1e9f;
#pragma unroll
                for (int hh = 0; hh < 2; hh++) {
                    int idx = mi * 2 + hh;
                    float2 xd = *(const float2*)(xr[idx] + col);
                    float l0 = c[mi][nf][hh * 2 + 0] * 0.125f + mt0 + aqv[idx] * xd.x + bqv[idx] * xd.x * xd.x;
                    float l1 = c[mi][nf][hh * 2 + 1] * 0.125f + mt1 + aqv[idx] * xd.y + bqv[idx] * xd.y * xd.y;
                    *(float2*)(lrow[idx] + col) = make_float2(l0, l1);
                    float mx = fmaxf(l0, l1);
                    if (mx > rm[idx]) { rs[idx] *= __expf(rm[idx] - mx); rm[idx] = mx; }
                    rs[idx] += __expf(l0 - rm[idx]) + __expf(l1 - rm[idx]);
                }
            }
    }

    // quad reduce
#pragma unroll
    for (int off = 1; off <= 2; off <<= 1)
#pragma unroll
        for (int i = 0; i < 4; i++) {
            float om = __shfl_xor_sync(0xffffffff, rm[i], off);
            float os = __shfl_xor_sync(0xffffffff, rs[i], off);
            float nm = fmaxf(rm[i], om);
            rs[i] = rs[i] * __expf(rm[i] - nm) + os * __expf(om - nm);
            rm[i] = nm;
        }
    __syncthreads();
    float2* red = (float2*)sm;
    if (t == 0) {
#pragma unroll
        for (int i = 0; i < 4; i++) {
            int rl = (i >> 1) * 16 + (i & 1) * 8 + g;
            red[w * 32 + rl] = make_float2(rm[i], rs[i]);
        }
    }
    __syncthreads();
    if (!(w & 1) && t == 0) {
#pragma unroll
        for (int i = 0; i < 4; i++) {
            int rl = (i >> 1) * 16 + (i & 1) * 8 + g;
            float2 p = red[(w ^ 1) * 32 + rl];
            float nm = fmaxf(rm[i], p.x);
            float ns = rs[i] * __expf(rm[i] - nm) + p.y * __expf(p.x - nm);
            int q = qb + wm + rl;
            g_rmax[bh * Sc + q] = nm;
            g_rinv[bh * Sc + q] = 1.0f / ns;
        }
    }
}

// ============================================================
// K4: attnV — read raw logits, normalize, write attn, P@V.
// grid = (16 qtile, 16 bh), block = 256.
// ============================================================
static constexpr int RSV = 68;
__global__ __launch_bounds__(256, 2)
void attnv_tc_kernel(float* __restrict__ attn)
{
    __shared__ uint32_t sm[8704];                 // VH 4352 + VL 4352 words
    const int VH_O = 0, VL_O = 4352;
    const int tid = threadIdx.x, w = tid >> 5, lane = tid & 31;
    const int g = lane >> 2, t = lane & 3;
    const int bh = blockIdx.y;
    const int qb = blockIdx.x * 128;
    const int wm = (w >> 1) * 32, wn = (w & 1) * 64;
    const uint32_t sbase = smem_u32(sm);

    float msv[4], invv[4];
    float* arow[4];
#pragma unroll
    for (int mi = 0; mi < 2; mi++)
#pragma unroll
        for (int hh = 0; hh < 2; hh++) {
            int idx = mi * 2 + hh;
            int q = qb + wm + mi * 16 + hh * 8 + g;
            msv[idx] = g_rmax[bh * Sc + q];
            invv[idx] = g_rinv[bh * Sc + q];
            arow[idx] = attn + ((size_t)bh * Sc + q) * Sc;
        }

    float o[2][8][4];
#pragma unroll
    for (int mi = 0; mi < 2; mi++)
#pragma unroll
        for (int nf = 0; nf < 8; nf++)
#pragma unroll
            for (int r = 0; r < 4; r++) o[mi][nf][r] = 0.f;

    const int vrow = tid >> 2, vseg = tid & 3;    // 64 d-rows, 4 segs

    for (int kt = 0; kt < 16; kt++) {
        const int kb = kt * 128;
        // stage V^T tile (64 d x 128 k) hi/lo from preconverted transposed arrays
        {
            const uint4* sH = (const uint4*)g_vth + ((size_t)(bh * DHc + vrow) * Sc + kb) / 8;
            const uint4* sL = (const uint4*)g_vtl + ((size_t)(bh * DHc + vrow) * Sc + kb) / 8;
            uint4* dH = (uint4*)(sm + VH_O + vrow * RSV);
            uint4* dL = (uint4*)(sm + VL_O + vrow * RSV);
#pragma unroll
            for (int i = 0; i < 4; i++) {
                dH[vseg * 4 + i] = sH[vseg * 4 + i];
                dL[vseg * 4 + i] = sL[vseg * 4 + i];
            }
        }
        __syncthreads();

#pragma unroll
        for (int j = 0; j < 4; j++) {
            uint32_t pah[2][4], pal[2][4];
#pragma unroll
            for (int mi = 0; mi < 2; mi++)
#pragma unroll
                for (int nn = 0; nn < 2; nn++) {
                    int col = kb + wn + (2 * j + nn) * 8 + 2 * t;
#pragma unroll
                    for (int hh = 0; hh < 2; hh++) {
                        int idx = mi * 2 + hh;
                        float2 L = *(const float2*)(arow[idx] + col);
                        float p0 = __expf(L.x - msv[idx]) * invv[idx];
                        float p1 = __expf(L.y - msv[idx]) * invv[idx];
                        *(float2*)(arow[idx] + col) = make_float2(p0, p1);
                        split2(p0, p1, pah[mi][nn * 2 + hh], pal[mi][nn * 2 + hh]);
                    }
                }
#pragma unroll
            for (int nd = 0; nd < 4; nd++) {
                uint32_t vh[4], vl[4];
                ldsm4(vh, addrB(sbase + VH_O * 4, nd * 16, wn + j * 16, lane, RSV));
                ldsm4(vl, addrB(sbase + VL_O * 4, nd * 16, wn + j * 16, lane, RSV));
#pragma unroll
                for (int mi = 0; mi < 2; mi++) {
                    mma16816(o[mi][2 * nd],     pah[mi], vh[0], vh[1]);
                    mma16816(o[mi][2 * nd],     pah[mi], vl[0], vl[1]);
                    mma16816(o[mi][2 * nd],     pal[mi], vh[0], vh[1]);
                    mma16816(o[mi][2 * nd + 1], pah[mi], vh[2], vh[3]);
                    mma16816(o[mi][2 * nd + 1], pah[mi], vl[2], vl[3]);
                    mma16816(o[mi][2 * nd + 1], pal[mi], vh[2], vh[3]);
                }
            }
        }
        __syncthreads();
    }

    // reduce across warp pairs (two k-halves)
    float* red = (float*)sm;
    if (w & 1) {
        float* dst = red + ((w >> 1) * 32 + lane) * 65;
#pragma unroll
        for (int mi = 0; mi < 2; mi++)
#pragma unroll
            for (int nf = 0; nf < 8; nf++)
#pragma unroll
                for (int r = 0; r < 4; r++)
                    dst[mi * 32 + nf * 4 + r] = o[mi][nf][r];
    }
    __syncthreads();
    if (!(w & 1)) {
        const int b = bh >> 3, h = bh & 7;
        const float* src = red + ((w >> 1) * 32 + lane) * 65;
#pragma unroll
        for (int mi = 0; mi < 2; mi++)
#pragma unroll
            for (int nf = 0; nf < 8; nf++)
#pragma unroll
                for (int r = 0; r < 4; r++)
                    o[mi][nf][r] += src[mi * 32 + nf * 4 + r];
#pragma unroll
        for (int mi = 0; mi < 2; mi++)
#pragma unroll
            for (int hh = 0; hh < 2; hh++) {
                int q = qb + wm + mi * 16 + hh * 8 + g;
#pragma unroll
                for (int nf = 0; nf < 8; nf++) {
                    float2 val = make_float2(o[mi][nf][hh * 2 + 0], o[mi][nf][hh * 2 + 1]);
                    *(float2*)(g_outpre + (size_t)(b * Sc + q) * DMc + h * DHc + nf * 8 + 2 * t) = val;
                }
            }
    }
}

// ============================================================
extern "C" void kernel_launch(void* const* d_in, const int* in_sizes, int n_in,
                              void* d_out, int out_size)
{
    const float* q     = (const float*)d_in[0];
    const float* k     = (const float*)d_in[1];
    const float* v     = (const float*)d_in[2];
    const float* xdiff = (const float*)d_in[3];
    const int*   mask  = (const int*)d_in[4];
    const float* Wq = (const float*)d_in[5];
    const float* bq = (const float*)d_in[6];
    const float* Wk = (const float*)d_in[7];
    const float* bk = (const float*)d_in[8];
    const float* Wv = (const float*)d_in[9];
    const float* bv = (const float*)d_in[10];
    const float* Wa = (const float*)d_in[11];
    const float* ba = (const float*)d_in[12];
    const float* Wb = (const float*)d_in[13];
    const float* bb = (const float*)d_in[14];
    const float* Wo = (const float*)d_in[15];
    const float* bo = (const float*)d_in[16];

    float* out  = (float*)d_out;                 // (B,S,DM)
    float* attn = out + (size_t)Bc * Sc * DMc;   // (B,H,S,S)

    cudaFuncSetAttribute(stats_tc_kernel, cudaFuncAttributeMaxDynamicSharedMemorySize, DYN_SMEM);

    qkv_kernel<<<dim3(DMc / 128, Mrows / 128, 3), 256>>>(q, k, v, Wq, Wk, Wv, bq, bk, bv);
    ab_kernel<<<Mrows / 32, 256>>>(Wa, ba, Wb, bb);
    stats_tc_kernel<<<dim3(Sc / 128, BHc), 256, DYN_SMEM>>>(xdiff, mask, attn);
    attnv_tc_kernel<<<dim3(Sc / 128, BHc), 256>>>(attn);
    out_kernel<<<dim3(DMc / 128, Mrows / 128), 256>>>(Wo, bo, out);
}